// round 6
// baseline (speedup 1.0000x reference)
#include <cuda_runtime.h>
#include <cuda_bf16.h>

// Problem constants
#define B    32
#define LQ   32
#define DLEN 4096
#define P    16
#define D    2048
#define H    2048
#define V    50257
#define VPAD 50432            // 394 * 128

#define KSPLIT 32             // k-split for skinny GEMMs
#define TILE_N 64
#define KB     64
#define MT     128            // ygemm rows per block
#define KT     32             // ygemm k-tile

// ---------------- scratch (device globals; no allocation allowed) ----------------
__device__ float g_qrep[B * D];
__device__ float g_qenc[B * H];
__device__ float g_v[B * D];
__device__ float g_part[KSPLIT * B * 2048];      // GEMM partials (8 MB)
__device__ float g_c[B];
__device__ unsigned char g_flag[VPAD];           // zero-init at load; self-cleaned by compact
__device__ int   g_ids[VPAD];
__device__ int   g_rank[V];
__device__ int   g_nids;
__device__ float g_y[(size_t)VPAD * B];          // dot table (6.5 MB)

// ---------------- f32x2 helpers (sm_103a packed fp32) ----------------
__device__ __forceinline__ unsigned long long ffma2(unsigned long long a,
                                                    unsigned long long b,
                                                    unsigned long long c) {
    unsigned long long d;
    asm("fma.rn.f32x2 %0, %1, %2, %3;" : "=l"(d) : "l"(a), "l"(b), "l"(c));
    return d;
}
__device__ __forceinline__ unsigned long long pack2(float x, float y) {
    unsigned long long r;
    asm("mov.b64 %0, {%1, %2};" : "=l"(r) : "f"(x), "f"(y));
    return r;
}
__device__ __forceinline__ float2 unpack2(unsigned long long v) {
    float2 r;
    asm("mov.b64 {%0, %1}, %2;" : "=f"(r.x), "=f"(r.y) : "l"(v));
    return r;
}

// ---------------- mark used vocab ids (also zeroes g_nids) ----------------
__global__ void k_mark(const int* __restrict__ docs,
                       const int* __restrict__ plen) {
    int b = blockIdx.x;
    __shared__ int tot;
    if (threadIdx.x == 0) {
        int s = 0;
        #pragma unroll
        for (int q = 0; q < P; q++) s += plen[b * P + q];
        tot = s;
        if (b == 0) g_nids = 0;   // no reader until k_compact (next kernel)
    }
    __syncthreads();
    for (int tt = threadIdx.x; tt < tot; tt += blockDim.x)
        g_flag[docs[b * DLEN + tt]] = 1;
}

// ---------------- compact used ids; self-clean flags for next call ----------------
__global__ void k_compact() {
    int i = blockIdx.x * 256 + threadIdx.x;
    if (i < V && g_flag[i]) {
        g_flag[i] = 0;
        int slot = atomicAdd(&g_nids, 1);
        g_ids[slot] = i;
        g_rank[i] = slot;
    }
}

// ---------------- q_rep = masked mean of query token embeddings ----------------
__global__ void k_qrep(const int* __restrict__ queries,
                       const int* __restrict__ qlen,
                       const float* __restrict__ emb) {
    int b = blockIdx.x;
    __shared__ int toks[LQ];
    if (threadIdx.x < LQ) toks[threadIdx.x] = queries[b * LQ + threadIdx.x];
    int len = qlen[b];
    __syncthreads();
    float inv = 1.0f / (float)len;
    int d = blockIdx.y * 256 + threadIdx.x;
    float s = 0.0f;
    for (int l = 0; l < len; l++) s += emb[(size_t)toks[l] * D + d];
    g_qrep[b * D + d] = s * inv;
}

// ---------------- skinny GEMM  C[32,2048] = A[32,2048] x W (optionally transposed) ----
__global__ void k_gemm(const float* __restrict__ A,
                       const float* __restrict__ W,
                       int transW) {
    const int n0 = blockIdx.x * TILE_N;
    const int k0 = blockIdx.y * (2048 / KSPLIT);   // chunk = 64 = KB (single iter)
    __shared__ float As[32][KB];
    __shared__ float Ws[TILE_N][KB + 1];

    const int t  = threadIdx.x;
    const int tb = t >> 5;
    const int tn = t & 31;

    float acc00 = 0.f, acc01 = 0.f, acc10 = 0.f, acc11 = 0.f;
    float acc20 = 0.f, acc21 = 0.f, acc30 = 0.f, acc31 = 0.f;

    {
        const int kbase = k0;
        #pragma unroll
        for (int i = 0; i < 8; i++) {
            int flat = t + i * 256;
            int bb = flat >> 6, kk = flat & 63;
            As[bb][kk] = A[bb * 2048 + kbase + kk];
        }
        if (!transW) {
            #pragma unroll
            for (int i = 0; i < 16; i++) {
                int flat = t + i * 256;
                int nn = flat >> 6, kk = flat & 63;
                Ws[nn][kk] = W[(size_t)(n0 + nn) * 2048 + kbase + kk];
            }
        } else {
            #pragma unroll
            for (int i = 0; i < 16; i++) {
                int flat = t + i * 256;
                int nn = flat & 63, kk = flat >> 6;
                Ws[nn][kk] = W[(size_t)(kbase + kk) * 2048 + n0 + nn];
            }
        }
        __syncthreads();

        #pragma unroll 16
        for (int k = 0; k < KB; k++) {
            float a0 = As[tb * 4 + 0][k];
            float a1 = As[tb * 4 + 1][k];
            float a2 = As[tb * 4 + 2][k];
            float a3 = As[tb * 4 + 3][k];
            float w0 = Ws[tn][k];
            float w1 = Ws[tn + 32][k];
            acc00 += a0 * w0; acc01 += a0 * w1;
            acc10 += a1 * w0; acc11 += a1 * w1;
            acc20 += a2 * w0; acc21 += a2 * w1;
            acc30 += a3 * w0; acc31 += a3 * w1;
        }
    }

    float* out = g_part + (size_t)blockIdx.y * 32 * 2048;
    out[(tb * 4 + 0) * 2048 + n0 + tn]      = acc00;
    out[(tb * 4 + 0) * 2048 + n0 + tn + 32] = acc01;
    out[(tb * 4 + 1) * 2048 + n0 + tn]      = acc10;
    out[(tb * 4 + 1) * 2048 + n0 + tn + 32] = acc11;
    out[(tb * 4 + 2) * 2048 + n0 + tn]      = acc20;
    out[(tb * 4 + 2) * 2048 + n0 + tn + 32] = acc21;
    out[(tb * 4 + 3) * 2048 + n0 + tn]      = acc30;
    out[(tb * 4 + 3) * 2048 + n0 + tn + 32] = acc31;
}

// vectorized partial reduce over 16384 float4
__global__ void k_reduce(float* __restrict__ C,
                         const float* __restrict__ bias,
                         int addBias) {
    int idx = blockIdx.x * 256 + threadIdx.x;
    const float4* part4 = (const float4*)g_part;
    float4 s = make_float4(0.f, 0.f, 0.f, 0.f);
    #pragma unroll
    for (int sp = 0; sp < KSPLIT; sp++) {
        float4 x = part4[sp * 16384 + idx];
        s.x += x.x; s.y += x.y; s.z += x.z; s.w += x.w;
    }
    if (addBias) {
        float4 bb = ((const float4*)bias)[idx & 511];
        s.x += bb.x; s.y += bb.y; s.z += bb.z; s.w += bb.w;
    }
    ((float4*)C)[idx] = s;
}

// c[b] = q_enc[b] . bias
__global__ void k_qc(const float* __restrict__ bias) {
    int b = blockIdx.x;
    float s = 0.0f;
    for (int i = threadIdx.x; i < H; i += 256) s += g_qenc[b * H + i] * bias[i];
    __shared__ float red[256];
    red[threadIdx.x] = s;
    __syncthreads();
    for (int o = 128; o; o >>= 1) {
        if (threadIdx.x < o) red[threadIdx.x] += red[threadIdx.x + o];
        __syncthreads();
    }
    if (threadIdx.x == 0) g_c[b] = red[0];
}

// ---------------- y[i, b] = emb[ids[i]] . v[b]  (tiled fp32x2 GEMM) ----------------
// block: 256 threads, tile M=128 (compact rows) x N=32 (batches), K looped by 32.
// thread (tm = t&15, tn = t>>4): 8 rows (4 row-PAIRS as f32x2) x 2 cols.
__global__ __launch_bounds__(256) void k_ygemm(const float* __restrict__ emb) {
    const int m0 = blockIdx.x * MT;
    const int nids = g_nids;
    if (m0 >= nids) return;

    __shared__ __align__(16) unsigned long long As2[KT][68];  // [k][row-pair] (64 + pad)
    __shared__ __align__(16) unsigned long long Vs2[KT][32];  // [k][n] duplicated pairs
    __shared__ int ids_s[MT];

    const int t  = threadIdx.x;
    const int tm = t & 15;
    const int tn = t >> 4;

    if (t < MT) {
        int gi = m0 + t;
        ids_s[t] = g_ids[gi < nids ? gi : 0];
    }
    __syncthreads();

    const int r  = t >> 1;       // 0..127: which row this thread stages
    const int hf = t & 1;        // which 16-k half
    const float* rowp = emb + (size_t)ids_s[r] * D + hf * 16;
    float* Asf = (float*)As2;    // row stride 136 floats

    unsigned long long acc[4][2];
    #pragma unroll
    for (int i = 0; i < 4; i++) { acc[i][0] = 0ull; acc[i][1] = 0ull; }

    // prefetch for kt = 0
    float4 pf[4];
    float  pv[4];
    #pragma unroll
    for (int i = 0; i < 4; i++) pf[i] = *(const float4*)(rowp + i * 4);
    #pragma unroll
    for (int i = 0; i < 4; i++) {
        int idx = t + i * 256;
        int kk = idx >> 5, n = idx & 31;
        pv[i] = g_v[n * D + kk];
    }

    for (int kt = 0; kt < D; kt += KT) {
        // stage prefetched tile to smem
        #pragma unroll
        for (int i = 0; i < 4; i++) {
            int kk = hf * 16 + i * 4;
            Asf[(kk + 0) * 136 + r] = pf[i].x;
            Asf[(kk + 1) * 136 + r] = pf[i].y;
            Asf[(kk + 2) * 136 + r] = pf[i].z;
            Asf[(kk + 3) * 136 + r] = pf[i].w;
        }
        #pragma unroll
        for (int i = 0; i < 4; i++) {
            int idx = t + i * 256;
            int kk = idx >> 5, n = idx & 31;
            Vs2[kk][n] = pack2(pv[i], pv[i]);
        }
        __syncthreads();

        // prefetch next tile while computing
        if (kt + KT < D) {
            #pragma unroll
            for (int i = 0; i < 4; i++) pf[i] = *(const float4*)(rowp + kt + KT + i * 4);
            #pragma unroll
            for (int i = 0; i < 4; i++) {
                int idx = t + i * 256;
                int kk = idx >> 5, n = idx & 31;
                pv[i] = g_v[n * D + kt + KT + kk];
            }
        }

        #pragma unroll
        for (int k = 0; k < KT; k++) {
            ulonglong2 a01 = *(const ulonglong2*)&As2[k][tm * 4];
            ulonglong2 a23 = *(const ulonglong2*)&As2[k][tm * 4 + 2];
            ulonglong2 vd  = *(const ulonglong2*)&Vs2[k][tn * 2];
            acc[0][0] = ffma2(a01.x, vd.x, acc[0][0]);
            acc[0][1] = ffma2(a01.x, vd.y, acc[0][1]);
            acc[1][0] = ffma2(a01.y, vd.x, acc[1][0]);
            acc[1][1] = ffma2(a01.y, vd.y, acc[1][1]);
            acc[2][0] = ffma2(a23.x, vd.x, acc[2][0]);
            acc[2][1] = ffma2(a23.x, vd.y, acc[2][1]);
            acc[3][0] = ffma2(a23.y, vd.x, acc[3][0]);
            acc[3][1] = ffma2(a23.y, vd.y, acc[3][1]);
        }
        __syncthreads();
    }

    // store y: rows m0 + tm*8 + mp*2 + {0,1}, cols tn*2 + nn
    #pragma unroll
    for (int mp = 0; mp < 4; mp++) {
        int row = m0 + tm * 8 + mp * 2;
        #pragma unroll
        for (int nn = 0; nn < 2; nn++) {
            float2 val = unpack2(acc[mp][nn]);
            int col = tn * 2 + nn;
            g_y[(size_t)(row + 0) * B + col] = val.x;
            g_y[(size_t)(row + 1) * B + col] = val.y;
        }
    }
}

// ---------------- scatter: score[b,p] = mean_token y[rank[tok], b] + c[b] ----------
__global__ void k_scatter(const int* __restrict__ docs,
                          const int* __restrict__ plen,
                          float* __restrict__ out) {
    const int bp = blockIdx.x;           // 512 blocks
    const int b = bp >> 4, p = bp & 15;
    const int t = threadIdx.x;           // 128 threads
    __shared__ int info[2];
    __shared__ float red[128];

    if (t == 0) {
        int start = 0;
        for (int q = 0; q < p; q++) start += plen[b * P + q];
        info[0] = start;
        info[1] = plen[b * P + p];
    }
    __syncthreads();
    const int start = info[0], len = info[1];

    float s = 0.0f;
    for (int tt = t; tt < len; tt += 128) {
        int tok = docs[b * DLEN + start + tt];
        s += g_y[(size_t)g_rank[tok] * B + b];
    }
    red[t] = s;
    __syncthreads();
    for (int o = 64; o; o >>= 1) {
        if (t < o) red[t] += red[t + o];
        __syncthreads();
    }
    if (t == 0) {
        float denom = (float)(len > 0 ? len : 1);
        out[bp] = (len > 0) ? (red[0] / denom + g_c[b]) : 0.0f;
    }
}

// ---------------- launch ----------------
extern "C" void kernel_launch(void* const* d_in, const int* in_sizes, int n_in,
                              void* d_out, int out_size) {
    const int*   queries = (const int*)d_in[0];
    const int*   qlen    = (const int*)d_in[1];
    const int*   docs    = (const int*)d_in[2];
    const int*   plen    = (const int*)d_in[3];
    const float* emb     = (const float*)d_in[4];
    const float* W       = (const float*)d_in[5];
    const float* bias    = (const float*)d_in[6];
    float*       out     = (float*)d_out;

    float *qrep_p, *qenc_p, *v_p;
    cudaGetSymbolAddress((void**)&qrep_p, g_qrep);
    cudaGetSymbolAddress((void**)&qenc_p, g_qenc);
    cudaGetSymbolAddress((void**)&v_p, g_v);

    cudaStream_t s2;
    cudaStreamCreateWithFlags(&s2, cudaStreamNonBlocking);
    cudaEvent_t ef, ej;
    cudaEventCreateWithFlags(&ef, cudaEventDisableTiming);
    cudaEventCreateWithFlags(&ej, cudaEventDisableTiming);

    // fork: dedup pipeline on s2, encode chain on stream 0
    cudaEventRecord(ef, 0);
    cudaStreamWaitEvent(s2, ef, 0);
    k_mark<<<B, 256, 0, s2>>>(docs, plen);
    k_compact<<<(V + 255) / 256, 256, 0, s2>>>();
    cudaEventRecord(ej, s2);

    k_qrep<<<dim3(B, 8), 256>>>(queries, qlen, emb);
    k_gemm<<<dim3(2048 / TILE_N, KSPLIT), 256>>>(qrep_p, W, 0);
    k_reduce<<<64, 256>>>(qenc_p, bias, 1);
    k_gemm<<<dim3(2048 / TILE_N, KSPLIT), 256>>>(qenc_p, W, 1);
    k_reduce<<<64, 256>>>(v_p, bias, 0);
    k_qc<<<B, 256>>>(bias);

    // join: ygemm needs ids (s2) + v (stream 0)
    cudaStreamWaitEvent(0, ej, 0);
    k_ygemm<<<VPAD / MT, 256>>>(emb);
    k_scatter<<<B * P, 128>>>(docs, plen, out);
}

// round 7
// speedup vs baseline: 1.1410x; 1.1410x over previous
#include <cuda_runtime.h>
#include <cuda_bf16.h>

// Problem constants
#define B    32
#define LQ   32
#define DLEN 4096
#define P    16
#define D    2048
#define H    2048
#define V    50257
#define VPAD 50432            // 394 * 128

#define KSPLIT 32             // k-split for skinny GEMMs
#define TILE_N 64
#define KB     64
#define MT     128            // ygemm rows per block
#define KT     32             // ygemm k-tile

// ---------------- scratch (device globals; no allocation allowed) ----------------
__device__ float g_qrep[B * D];
__device__ float g_qenc[B * H];
__device__ float g_v[B * D];
__device__ float g_vt[D * B];                    // v transposed [d][b]
__device__ float g_part[KSPLIT * B * 2048];      // GEMM partials (8 MB)
__device__ float g_c[B];
__device__ unsigned char g_flag[VPAD];           // zero-init at load; self-cleaned by compact
__device__ int   g_ids[VPAD];
__device__ int   g_rank[V];
__device__ int   g_nids;
__device__ float g_y[(size_t)VPAD * B];          // dot table (6.5 MB)

// ---------------- f32x2 helpers (sm_103a packed fp32) ----------------
__device__ __forceinline__ unsigned long long ffma2(unsigned long long a,
                                                    unsigned long long b,
                                                    unsigned long long c) {
    unsigned long long d;
    asm("fma.rn.f32x2 %0, %1, %2, %3;" : "=l"(d) : "l"(a), "l"(b), "l"(c));
    return d;
}
__device__ __forceinline__ unsigned long long pack2(float x, float y) {
    unsigned long long r;
    asm("mov.b64 %0, {%1, %2};" : "=l"(r) : "f"(x), "f"(y));
    return r;
}
__device__ __forceinline__ float2 unpack2(unsigned long long v) {
    float2 r;
    asm("mov.b64 {%0, %1}, %2;" : "=f"(r.x), "=f"(r.y) : "l"(v));
    return r;
}

// ---------------- mark used vocab ids (also zeroes g_nids) ----------------
__global__ void k_mark(const int* __restrict__ docs,
                       const int* __restrict__ plen) {
    int b = blockIdx.x;
    __shared__ int tot;
    if (threadIdx.x == 0) {
        int s = 0;
        #pragma unroll
        for (int q = 0; q < P; q++) s += plen[b * P + q];
        tot = s;
        if (b == 0) g_nids = 0;   // no reader until k_compact (next kernel)
    }
    __syncthreads();
    for (int tt = threadIdx.x; tt < tot; tt += blockDim.x)
        g_flag[docs[b * DLEN + tt]] = 1;
}

// ---------------- compact used ids; block-aggregated atomics (197 total) ----------
__global__ void k_compact() {
    __shared__ int warp_off[8];
    __shared__ int block_base;
    int i = blockIdx.x * 256 + threadIdx.x;
    bool has = (i < V) && g_flag[i];
    if (has) g_flag[i] = 0;                      // self-clean for next call
    unsigned mask = __ballot_sync(0xFFFFFFFFu, has);
    int w = threadIdx.x >> 5, lane = threadIdx.x & 31;
    if (lane == 0) warp_off[w] = __popc(mask);
    __syncthreads();
    if (threadIdx.x == 0) {
        int tot = 0;
        #pragma unroll
        for (int j = 0; j < 8; j++) { int c = warp_off[j]; warp_off[j] = tot; tot += c; }
        block_base = tot ? atomicAdd(&g_nids, tot) : 0;
    }
    __syncthreads();
    if (has) {
        int slot = block_base + warp_off[w] + __popc(mask & ((1u << lane) - 1u));
        g_ids[slot] = i;
        g_rank[i] = slot;
    }
}

// ---------------- q_rep = masked mean of query token embeddings ----------------
__global__ void k_qrep(const int* __restrict__ queries,
                       const int* __restrict__ qlen,
                       const float* __restrict__ emb) {
    int b = blockIdx.x;
    __shared__ int toks[LQ];
    if (threadIdx.x < LQ) toks[threadIdx.x] = queries[b * LQ + threadIdx.x];
    int len = qlen[b];
    __syncthreads();
    float inv = 1.0f / (float)len;
    int d = blockIdx.y * 256 + threadIdx.x;
    float s = 0.0f;
    for (int l = 0; l < len; l++) s += emb[(size_t)toks[l] * D + d];
    g_qrep[b * D + d] = s * inv;
}

// ---------------- skinny GEMM  C[32,2048] = A[32,2048] x W (optionally transposed) ----
__global__ void k_gemm(const float* __restrict__ A,
                       const float* __restrict__ W,
                       int transW) {
    const int n0 = blockIdx.x * TILE_N;
    const int k0 = blockIdx.y * (2048 / KSPLIT);   // chunk = 64 = KB (single iter)
    __shared__ float As[32][KB];
    __shared__ float Ws[TILE_N][KB + 1];

    const int t  = threadIdx.x;
    const int tb = t >> 5;
    const int tn = t & 31;

    float acc00 = 0.f, acc01 = 0.f, acc10 = 0.f, acc11 = 0.f;
    float acc20 = 0.f, acc21 = 0.f, acc30 = 0.f, acc31 = 0.f;

    {
        const int kbase = k0;
        #pragma unroll
        for (int i = 0; i < 8; i++) {
            int flat = t + i * 256;
            int bb = flat >> 6, kk = flat & 63;
            As[bb][kk] = A[bb * 2048 + kbase + kk];
        }
        if (!transW) {
            #pragma unroll
            for (int i = 0; i < 16; i++) {
                int flat = t + i * 256;
                int nn = flat >> 6, kk = flat & 63;
                Ws[nn][kk] = W[(size_t)(n0 + nn) * 2048 + kbase + kk];
            }
        } else {
            #pragma unroll
            for (int i = 0; i < 16; i++) {
                int flat = t + i * 256;
                int nn = flat & 63, kk = flat >> 6;
                Ws[nn][kk] = W[(size_t)(kbase + kk) * 2048 + n0 + nn];
            }
        }
        __syncthreads();

        #pragma unroll 16
        for (int k = 0; k < KB; k++) {
            float a0 = As[tb * 4 + 0][k];
            float a1 = As[tb * 4 + 1][k];
            float a2 = As[tb * 4 + 2][k];
            float a3 = As[tb * 4 + 3][k];
            float w0 = Ws[tn][k];
            float w1 = Ws[tn + 32][k];
            acc00 += a0 * w0; acc01 += a0 * w1;
            acc10 += a1 * w0; acc11 += a1 * w1;
            acc20 += a2 * w0; acc21 += a2 * w1;
            acc30 += a3 * w0; acc31 += a3 * w1;
        }
    }

    float* out = g_part + (size_t)blockIdx.y * 32 * 2048;
    out[(tb * 4 + 0) * 2048 + n0 + tn]      = acc00;
    out[(tb * 4 + 0) * 2048 + n0 + tn + 32] = acc01;
    out[(tb * 4 + 1) * 2048 + n0 + tn]      = acc10;
    out[(tb * 4 + 1) * 2048 + n0 + tn + 32] = acc11;
    out[(tb * 4 + 2) * 2048 + n0 + tn]      = acc20;
    out[(tb * 4 + 2) * 2048 + n0 + tn + 32] = acc21;
    out[(tb * 4 + 3) * 2048 + n0 + tn]      = acc30;
    out[(tb * 4 + 3) * 2048 + n0 + tn + 32] = acc31;
}

// vectorized partial reduce over 16384 float4
__global__ void k_reduce(float* __restrict__ C,
                         const float* __restrict__ bias,
                         int addBias) {
    int idx = blockIdx.x * 256 + threadIdx.x;
    const float4* part4 = (const float4*)g_part;
    float4 s = make_float4(0.f, 0.f, 0.f, 0.f);
    #pragma unroll
    for (int sp = 0; sp < KSPLIT; sp++) {
        float4 x = part4[sp * 16384 + idx];
        s.x += x.x; s.y += x.y; s.z += x.z; s.w += x.w;
    }
    if (addBias) {
        float4 bb = ((const float4*)bias)[idx & 511];
        s.x += bb.x; s.y += bb.y; s.z += bb.z; s.w += bb.w;
    }
    ((float4*)C)[idx] = s;
}

// transpose v -> g_vt[d*B + b]; coalesced reads, per-thread contiguous writes
__global__ void k_vt() {
    int d = blockIdx.x * 256 + threadIdx.x;      // grid 8 x 256
    float vals[B];
    #pragma unroll
    for (int b = 0; b < B; b++) vals[b] = g_v[b * D + d];
    float4* out = (float4*)(g_vt + (size_t)d * B);
    #pragma unroll
    for (int j = 0; j < B / 4; j++)
        out[j] = make_float4(vals[j * 4], vals[j * 4 + 1], vals[j * 4 + 2], vals[j * 4 + 3]);
}

// c[b] = q_enc[b] . bias
__global__ void k_qc(const float* __restrict__ bias) {
    int b = blockIdx.x;
    float s = 0.0f;
    for (int i = threadIdx.x; i < H; i += 256) s += g_qenc[b * H + i] * bias[i];
    __shared__ float red[256];
    red[threadIdx.x] = s;
    __syncthreads();
    for (int o = 128; o; o >>= 1) {
        if (threadIdx.x < o) red[threadIdx.x] += red[threadIdx.x + o];
        __syncthreads();
    }
    if (threadIdx.x == 0) g_c[b] = red[0];
}

// ---------------- y[i, b] = emb[ids[i]] . v[b]  (tiled fp32x2 GEMM) ----------------
// block: 256 threads, tile M=128 (compact rows) x N=32 (batches), K looped by 32.
// thread (tm = t&15, tn = t>>4): 8 rows (4 row-PAIRS as f32x2) x 2 cols.
__global__ __launch_bounds__(256) void k_ygemm(const float* __restrict__ emb) {
    const int m0 = blockIdx.x * MT;
    const int nids = g_nids;
    if (m0 >= nids) return;

    __shared__ __align__(16) unsigned long long As2[KT][68];  // [k][row-pair] (64 + pad)
    __shared__ __align__(16) unsigned long long Vs2[KT][32];  // [k][n] duplicated pairs
    __shared__ int ids_s[MT];

    const int t  = threadIdx.x;
    const int tm = t & 15;
    const int tn = t >> 4;

    if (t < MT) {
        int gi = m0 + t;
        ids_s[t] = g_ids[gi < nids ? gi : 0];
    }
    __syncthreads();

    const int r  = t >> 1;       // 0..127: which row this thread stages
    const int hf = t & 1;        // which 16-k half
    const float* rowp = emb + (size_t)ids_s[r] * D + hf * 16;
    float* Asf = (float*)As2;    // row stride 136 floats

    unsigned long long acc[4][2];
    #pragma unroll
    for (int i = 0; i < 4; i++) { acc[i][0] = 0ull; acc[i][1] = 0ull; }

    // prefetch for kt = 0  (vt loads coalesced: lane-consecutive b index)
    float4 pf[4];
    float  pv[4];
    #pragma unroll
    for (int i = 0; i < 4; i++) pf[i] = *(const float4*)(rowp + i * 4);
    #pragma unroll
    for (int i = 0; i < 4; i++) {
        int idx = t + i * 256;
        int kk = idx >> 5, n = idx & 31;
        pv[i] = g_vt[(size_t)kk * B + n];
    }

    for (int kt = 0; kt < D; kt += KT) {
        // stage prefetched tile to smem
        #pragma unroll
        for (int i = 0; i < 4; i++) {
            int kk = hf * 16 + i * 4;
            Asf[(kk + 0) * 136 + r] = pf[i].x;
            Asf[(kk + 1) * 136 + r] = pf[i].y;
            Asf[(kk + 2) * 136 + r] = pf[i].z;
            Asf[(kk + 3) * 136 + r] = pf[i].w;
        }
        #pragma unroll
        for (int i = 0; i < 4; i++) {
            int idx = t + i * 256;
            int kk = idx >> 5, n = idx & 31;
            Vs2[kk][n] = pack2(pv[i], pv[i]);
        }
        __syncthreads();

        // prefetch next tile while computing
        if (kt + KT < D) {
            #pragma unroll
            for (int i = 0; i < 4; i++) pf[i] = *(const float4*)(rowp + kt + KT + i * 4);
            #pragma unroll
            for (int i = 0; i < 4; i++) {
                int idx = t + i * 256;
                int kk = idx >> 5, n = idx & 31;
                pv[i] = g_vt[(size_t)(kt + KT + kk) * B + n];
            }
        }

        #pragma unroll
        for (int k = 0; k < KT; k++) {
            ulonglong2 a01 = *(const ulonglong2*)&As2[k][tm * 4];
            ulonglong2 a23 = *(const ulonglong2*)&As2[k][tm * 4 + 2];
            ulonglong2 vd  = *(const ulonglong2*)&Vs2[k][tn * 2];
            acc[0][0] = ffma2(a01.x, vd.x, acc[0][0]);
            acc[0][1] = ffma2(a01.x, vd.y, acc[0][1]);
            acc[1][0] = ffma2(a01.y, vd.x, acc[1][0]);
            acc[1][1] = ffma2(a01.y, vd.y, acc[1][1]);
            acc[2][0] = ffma2(a23.x, vd.x, acc[2][0]);
            acc[2][1] = ffma2(a23.x, vd.y, acc[2][1]);
            acc[3][0] = ffma2(a23.y, vd.x, acc[3][0]);
            acc[3][1] = ffma2(a23.y, vd.y, acc[3][1]);
        }
        __syncthreads();
    }

    // store y: rows m0 + tm*8 + mp*2 + {0,1}, cols tn*2 + nn
    #pragma unroll
    for (int mp = 0; mp < 4; mp++) {
        int row = m0 + tm * 8 + mp * 2;
        #pragma unroll
        for (int nn = 0; nn < 2; nn++) {
            float2 val = unpack2(acc[mp][nn]);
            int col = tn * 2 + nn;
            g_y[(size_t)(row + 0) * B + col] = val.x;
            g_y[(size_t)(row + 1) * B + col] = val.y;
        }
    }
}

// ---------------- scatter: score[b,p] = mean_token y[rank[tok], b] + c[b] ----------
__global__ void k_scatter(const int* __restrict__ docs,
                          const int* __restrict__ plen,
                          float* __restrict__ out) {
    const int bp = blockIdx.x;           // 512 blocks
    const int b = bp >> 4, p = bp & 15;
    const int t = threadIdx.x;           // 128 threads
    __shared__ int info[2];
    __shared__ float red[128];

    if (t == 0) {
        int start = 0;
        for (int q = 0; q < p; q++) start += plen[b * P + q];
        info[0] = start;
        info[1] = plen[b * P + p];
    }
    __syncthreads();
    const int start = info[0], len = info[1];

    float s = 0.0f;
    for (int tt = t; tt < len; tt += 128) {
        int tok = docs[b * DLEN + start + tt];
        s += g_y[(size_t)g_rank[tok] * B + b];
    }
    red[t] = s;
    __syncthreads();
    for (int o = 64; o; o >>= 1) {
        if (t < o) red[t] += red[t + o];
        __syncthreads();
    }
    if (t == 0) {
        float denom = (float)(len > 0 ? len : 1);
        out[bp] = (len > 0) ? (red[0] / denom + g_c[b]) : 0.0f;
    }
}

// ---------------- launch ----------------
extern "C" void kernel_launch(void* const* d_in, const int* in_sizes, int n_in,
                              void* d_out, int out_size) {
    const int*   queries = (const int*)d_in[0];
    const int*   qlen    = (const int*)d_in[1];
    const int*   docs    = (const int*)d_in[2];
    const int*   plen    = (const int*)d_in[3];
    const float* emb     = (const float*)d_in[4];
    const float* W       = (const float*)d_in[5];
    const float* bias    = (const float*)d_in[6];
    float*       out     = (float*)d_out;

    float *qrep_p, *qenc_p, *v_p;
    cudaGetSymbolAddress((void**)&qrep_p, g_qrep);
    cudaGetSymbolAddress((void**)&qenc_p, g_qenc);
    cudaGetSymbolAddress((void**)&v_p, g_v);

    cudaStream_t s2;
    cudaStreamCreateWithFlags(&s2, cudaStreamNonBlocking);
    cudaEvent_t ef, ej;
    cudaEventCreateWithFlags(&ef, cudaEventDisableTiming);
    cudaEventCreateWithFlags(&ej, cudaEventDisableTiming);

    // fork: dedup pipeline on s2, encode chain on stream 0
    cudaEventRecord(ef, 0);
    cudaStreamWaitEvent(s2, ef, 0);
    k_mark<<<B, 256, 0, s2>>>(docs, plen);
    k_compact<<<(V + 255) / 256, 256, 0, s2>>>();
    cudaEventRecord(ej, s2);

    k_qrep<<<dim3(B, 8), 256>>>(queries, qlen, emb);
    k_gemm<<<dim3(2048 / TILE_N, KSPLIT), 256>>>(qrep_p, W, 0);
    k_reduce<<<64, 256>>>(qenc_p, bias, 1);
    k_gemm<<<dim3(2048 / TILE_N, KSPLIT), 256>>>(qenc_p, W, 1);
    k_reduce<<<64, 256>>>(v_p, bias, 0);
    k_vt<<<8, 256>>>();
    k_qc<<<B, 256>>>(bias);

    // join: ygemm needs ids (s2) + vt (stream 0)
    cudaStreamWaitEvent(0, ej, 0);
    k_ygemm<<<VPAD / MT, 256>>>(emb);
    k_scatter<<<B * P, 128>>>(docs, plen, out);
}

// round 8
// speedup vs baseline: 4.5272x; 3.9678x over previous
#include <cuda_runtime.h>
#include <cuda_bf16.h>

// Problem constants
#define B    32
#define LQ   32
#define DLEN 4096
#define P    16
#define D    2048
#define H    2048
#define V    50257
#define VPAD 50432            // 394 * 128

#define KSPLIT 32             // k-split for skinny GEMMs
#define TILE_N 64
#define KB     64
#define KCH    8              // k-chunks in ydot (256 d's each)

// ---------------- scratch (device globals; no allocation allowed) ----------------
__device__ float g_qrep[B * D];
__device__ float g_qenc[B * H];
__device__ float g_v[B * D];
__device__ float g_part[KSPLIT * B * 2048];      // GEMM partials (8 MB)
__device__ float g_c[B];
__device__ unsigned int g_mask[VPAD];            // per-id batch mask; self-cleaned
__device__ int   g_ids[VPAD];
__device__ unsigned int g_cmask[VPAD];
__device__ int   g_rank[V];
__device__ int   g_nids;
__device__ float g_yp[(size_t)VPAD * 256];       // chunk partials [slot][z*32+b]

// ---------------- mark: batch mask per used vocab id (also zeroes g_nids) ----------
__global__ void k_mark(const int* __restrict__ docs,
                       const int* __restrict__ plen) {
    int b = blockIdx.x;
    __shared__ int tot;
    if (threadIdx.x == 0) {
        int s = 0;
        #pragma unroll
        for (int q = 0; q < P; q++) s += plen[b * P + q];
        tot = s;
        if (b == 0) g_nids = 0;   // no reader until k_compact (next kernel)
    }
    __syncthreads();
    unsigned bit = 1u << b;
    for (int tt = threadIdx.x; tt < tot; tt += blockDim.x)
        atomicOr(&g_mask[docs[b * DLEN + tt]], bit);
}

// ---------------- compact used ids + masks; block-aggregated atomics ---------------
__global__ void k_compact() {
    __shared__ int warp_off[8];
    __shared__ int block_base;
    int i = blockIdx.x * 256 + threadIdx.x;
    unsigned m = (i < V) ? g_mask[i] : 0u;
    bool has = (m != 0u);
    if (has) g_mask[i] = 0u;                     // self-clean for next call
    unsigned ballot = __ballot_sync(0xFFFFFFFFu, has);
    int w = threadIdx.x >> 5, lane = threadIdx.x & 31;
    if (lane == 0) warp_off[w] = __popc(ballot);
    __syncthreads();
    if (threadIdx.x == 0) {
        int tot = 0;
        #pragma unroll
        for (int j = 0; j < 8; j++) { int c = warp_off[j]; warp_off[j] = tot; tot += c; }
        block_base = tot ? atomicAdd(&g_nids, tot) : 0;
    }
    __syncthreads();
    if (has) {
        int slot = block_base + warp_off[w] + __popc(ballot & ((1u << lane) - 1u));
        g_ids[slot] = i;
        g_cmask[slot] = m;
        g_rank[i] = slot;
    }
}

// ---------------- q_rep = masked mean of query token embeddings ----------------
__global__ void k_qrep(const int* __restrict__ queries,
                       const int* __restrict__ qlen,
                       const float* __restrict__ emb) {
    int b = blockIdx.x;
    __shared__ int toks[LQ];
    if (threadIdx.x < LQ) toks[threadIdx.x] = queries[b * LQ + threadIdx.x];
    int len = qlen[b];
    __syncthreads();
    float inv = 1.0f / (float)len;
    int d = blockIdx.y * 256 + threadIdx.x;
    float s = 0.0f;
    for (int l = 0; l < len; l++) s += emb[(size_t)toks[l] * D + d];
    g_qrep[b * D + d] = s * inv;
}

// ---------------- skinny GEMM  C[32,2048] = A[32,2048] x W (optionally transposed) ----
__global__ void k_gemm(const float* __restrict__ A,
                       const float* __restrict__ W,
                       int transW) {
    const int n0 = blockIdx.x * TILE_N;
    const int k0 = blockIdx.y * (2048 / KSPLIT);   // chunk = 64 = KB (single iter)
    __shared__ float As[32][KB];
    __shared__ float Ws[TILE_N][KB + 1];

    const int t  = threadIdx.x;
    const int tb = t >> 5;
    const int tn = t & 31;

    float acc00 = 0.f, acc01 = 0.f, acc10 = 0.f, acc11 = 0.f;
    float acc20 = 0.f, acc21 = 0.f, acc30 = 0.f, acc31 = 0.f;

    {
        const int kbase = k0;
        #pragma unroll
        for (int i = 0; i < 8; i++) {
            int flat = t + i * 256;
            int bb = flat >> 6, kk = flat & 63;
            As[bb][kk] = A[bb * 2048 + kbase + kk];
        }
        if (!transW) {
            #pragma unroll
            for (int i = 0; i < 16; i++) {
                int flat = t + i * 256;
                int nn = flat >> 6, kk = flat & 63;
                Ws[nn][kk] = W[(size_t)(n0 + nn) * 2048 + kbase + kk];
            }
        } else {
            #pragma unroll
            for (int i = 0; i < 16; i++) {
                int flat = t + i * 256;
                int nn = flat & 63, kk = flat >> 6;
                Ws[nn][kk] = W[(size_t)(kbase + kk) * 2048 + n0 + nn];
            }
        }
        __syncthreads();

        #pragma unroll 16
        for (int k = 0; k < KB; k++) {
            float a0 = As[tb * 4 + 0][k];
            float a1 = As[tb * 4 + 1][k];
            float a2 = As[tb * 4 + 2][k];
            float a3 = As[tb * 4 + 3][k];
            float w0 = Ws[tn][k];
            float w1 = Ws[tn + 32][k];
            acc00 += a0 * w0; acc01 += a0 * w1;
            acc10 += a1 * w0; acc11 += a1 * w1;
            acc20 += a2 * w0; acc21 += a2 * w1;
            acc30 += a3 * w0; acc31 += a3 * w1;
        }
    }

    float* out = g_part + (size_t)blockIdx.y * 32 * 2048;
    out[(tb * 4 + 0) * 2048 + n0 + tn]      = acc00;
    out[(tb * 4 + 0) * 2048 + n0 + tn + 32] = acc01;
    out[(tb * 4 + 1) * 2048 + n0 + tn]      = acc10;
    out[(tb * 4 + 1) * 2048 + n0 + tn + 32] = acc11;
    out[(tb * 4 + 2) * 2048 + n0 + tn]      = acc20;
    out[(tb * 4 + 2) * 2048 + n0 + tn + 32] = acc21;
    out[(tb * 4 + 3) * 2048 + n0 + tn]      = acc30;
    out[(tb * 4 + 3) * 2048 + n0 + tn + 32] = acc31;
}

// vectorized partial reduce over 16384 float4; 128 blocks x 128 threads
__global__ void k_reduce(float* __restrict__ C,
                         const float* __restrict__ bias,
                         int addBias) {
    int idx = blockIdx.x * 128 + threadIdx.x;
    const float4* part4 = (const float4*)g_part;
    float4 s = make_float4(0.f, 0.f, 0.f, 0.f);
    #pragma unroll
    for (int sp = 0; sp < KSPLIT; sp++) {
        float4 x = part4[sp * 16384 + idx];
        s.x += x.x; s.y += x.y; s.z += x.z; s.w += x.w;
    }
    if (addBias) {
        float4 bb = ((const float4*)bias)[idx & 511];
        s.x += bb.x; s.y += bb.y; s.z += bb.z; s.w += bb.w;
    }
    ((float4*)C)[idx] = s;
}

// c[b] = q_enc[b] . bias
__global__ void k_qc(const float* __restrict__ bias) {
    int b = blockIdx.x;
    float s = 0.0f;
    for (int i = threadIdx.x; i < H; i += 256) s += g_qenc[b * H + i] * bias[i];
    __shared__ float red[256];
    red[threadIdx.x] = s;
    __syncthreads();
    for (int o = 128; o; o >>= 1) {
        if (threadIdx.x < o) red[threadIdx.x] += red[threadIdx.x + o];
        __syncthreads();
    }
    if (threadIdx.x == 0) g_c[b] = red[0];
}

// ---------------- ydot: per compact row, dot against ONLY the batches in its mask ----
// grid (VPAD/128, KCH). Block stages v k-chunk (32 KB) once; one warp per row,
// double-buffered row loads; ~1.86 batches per row avg.
__global__ __launch_bounds__(256) void k_ydot(const float* __restrict__ emb) {
    const int z  = blockIdx.y;
    const int m0 = blockIdx.x * 128;
    const int nids = g_nids;
    if (m0 >= nids) return;

    __shared__ float vs[32][256];    // v chunk [b][j]
    __shared__ int ids_s[128];
    __shared__ unsigned mask_s[128];

    const int t = threadIdx.x, w = t >> 5, lane = t & 31;

    #pragma unroll
    for (int i = 0; i < 8; i++) {
        int idx = t + i * 256;               // 0..2047 float4s
        int b = idx >> 6, j = idx & 63;
        *((float4*)&vs[b][j * 4]) = *(const float4*)(g_v + (size_t)b * D + z * 256 + j * 4);
    }
    if (t < 128) {
        int gi = m0 + t;
        bool val = gi < nids;
        ids_s[t]  = val ? g_ids[gi] : 0;
        mask_s[t] = val ? g_cmask[gi] : 0u;
    }
    __syncthreads();

    const int rbase = w * 16;
    float4 pa, pb;
    {
        const float* rp = emb + (size_t)ids_s[rbase] * D + z * 256 + lane * 8;
        pa = *(const float4*)rp;
        pb = *(const float4*)(rp + 4);
    }
    #pragma unroll 1
    for (int r = 0; r < 16; r++) {
        float4 ea = pa, eb = pb;
        unsigned mask = mask_s[rbase + r];
        int slot = m0 + rbase + r;
        if (r + 1 < 16) {
            const float* rp = emb + (size_t)ids_s[rbase + r + 1] * D + z * 256 + lane * 8;
            pa = *(const float4*)rp;
            pb = *(const float4*)(rp + 4);
        }
        while (mask) {
            int b = __ffs(mask) - 1;
            mask &= mask - 1;
            const float* vp = &vs[b][lane * 8];
            float s = ea.x * vp[0] + ea.y * vp[1] + ea.z * vp[2] + ea.w * vp[3]
                    + eb.x * vp[4] + eb.y * vp[5] + eb.z * vp[6] + eb.w * vp[7];
            #pragma unroll
            for (int o = 16; o; o >>= 1) s += __shfl_xor_sync(0xFFFFFFFFu, s, o);
            if (lane == 0) g_yp[(size_t)slot * 256 + z * 32 + b] = s;
        }
    }
}

// ---------------- scatter: score[b,p] = mean_token sum_z yp[rank[tok]][z][b] + c[b] --
__global__ void k_scatter(const int* __restrict__ docs,
                          const int* __restrict__ plen,
                          float* __restrict__ out) {
    const int bp = blockIdx.x;           // 512 blocks
    const int b = bp >> 4, p = bp & 15;
    const int t = threadIdx.x;           // 128 threads
    __shared__ int info[2];
    __shared__ float red[128];

    if (t == 0) {
        int start = 0;
        for (int q = 0; q < p; q++) start += plen[b * P + q];
        info[0] = start;
        info[1] = plen[b * P + p];
    }
    __syncthreads();
    const int start = info[0], len = info[1];

    float s = 0.0f;
    for (int tt = t; tt < len; tt += 128) {
        int tok = docs[b * DLEN + start + tt];
        const float* yb = g_yp + (size_t)g_rank[tok] * 256 + b;
        // fixed summation order over the 8 k-chunks -> deterministic
        float s01 = yb[0 * 32] + yb[1 * 32];
        float s23 = yb[2 * 32] + yb[3 * 32];
        float s45 = yb[4 * 32] + yb[5 * 32];
        float s67 = yb[6 * 32] + yb[7 * 32];
        s += (s01 + s23) + (s45 + s67);
    }
    red[t] = s;
    __syncthreads();
    for (int o = 64; o; o >>= 1) {
        if (t < o) red[t] += red[t + o];
        __syncthreads();
    }
    if (t == 0) {
        float denom = (float)(len > 0 ? len : 1);
        out[bp] = (len > 0) ? (red[0] / denom + g_c[b]) : 0.0f;
    }
}

// ---------------- launch ----------------
extern "C" void kernel_launch(void* const* d_in, const int* in_sizes, int n_in,
                              void* d_out, int out_size) {
    const int*   queries = (const int*)d_in[0];
    const int*   qlen    = (const int*)d_in[1];
    const int*   docs    = (const int*)d_in[2];
    const int*   plen    = (const int*)d_in[3];
    const float* emb     = (const float*)d_in[4];
    const float* W       = (const float*)d_in[5];
    const float* bias    = (const float*)d_in[6];
    float*       out     = (float*)d_out;

    float *qrep_p, *qenc_p, *v_p;
    cudaGetSymbolAddress((void**)&qrep_p, g_qrep);
    cudaGetSymbolAddress((void**)&qenc_p, g_qenc);
    cudaGetSymbolAddress((void**)&v_p, g_v);

    cudaStream_t s2;
    cudaStreamCreateWithFlags(&s2, cudaStreamNonBlocking);
    cudaEvent_t ef, ej;
    cudaEventCreateWithFlags(&ef, cudaEventDisableTiming);
    cudaEventCreateWithFlags(&ej, cudaEventDisableTiming);

    // fork: dedup pipeline on s2, encode chain on stream 0
    cudaEventRecord(ef, 0);
    cudaStreamWaitEvent(s2, ef, 0);
    k_mark<<<B, 256, 0, s2>>>(docs, plen);
    k_compact<<<(V + 255) / 256, 256, 0, s2>>>();
    cudaEventRecord(ej, s2);

    k_qrep<<<dim3(B, 8), 256>>>(queries, qlen, emb);
    k_gemm<<<dim3(2048 / TILE_N, KSPLIT), 256>>>(qrep_p, W, 0);
    k_reduce<<<128, 128>>>(qenc_p, bias, 1);
    k_gemm<<<dim3(2048 / TILE_N, KSPLIT), 256>>>(qenc_p, W, 1);
    k_reduce<<<128, 128>>>(v_p, bias, 0);
    k_qc<<<B, 256>>>(bias);

    // join: ydot needs ids+masks (s2) and v (stream 0)
    cudaStreamWaitEvent(0, ej, 0);
    k_ydot<<<dim3(VPAD / 128, KCH), 256>>>(emb);
    k_scatter<<<B * P, 128>>>(docs, plen, out);
}

// round 9
// speedup vs baseline: 4.6054x; 1.0173x over previous
#include <cuda_runtime.h>
#include <cuda_bf16.h>

// Problem constants
#define B    32
#define LQ   32
#define DLEN 4096
#define P    16
#define D    2048
#define H    2048
#define V    50257
#define VPAD 50432            // 394 * 128

#define KSPLIT 32             // k-split for skinny GEMMs
#define TILE_N 64
#define KB     64
#define KCH    8              // k-chunks in ydot (256 d's each)
#define YROWS  256            // compact rows per ydot block

// ---------------- scratch (device globals; no allocation allowed) ----------------
__device__ float g_qrep[B * D];
__device__ float g_qenc[B * H];
__device__ float g_v[B * D];
__device__ float g_part[KSPLIT * B * 2048];      // GEMM partials (8 MB)
__device__ float g_c[B];
__device__ unsigned int g_mask[VPAD];            // per-id batch mask; self-cleaned
__device__ int   g_ids[VPAD];
__device__ unsigned int g_cmask[VPAD];
__device__ int   g_rank[V];
__device__ int   g_nids;
__device__ float g_yp[(size_t)VPAD * 256];       // chunk partials [slot][z*32+b]

// ---------------- f32x2 helpers (sm_103a packed fp32; same rounding as scalar) ------
__device__ __forceinline__ unsigned long long ffma2(unsigned long long a,
                                                    unsigned long long b,
                                                    unsigned long long c) {
    unsigned long long d;
    asm("fma.rn.f32x2 %0, %1, %2, %3;" : "=l"(d) : "l"(a), "l"(b), "l"(c));
    return d;
}
__device__ __forceinline__ unsigned long long pack2(float x, float y) {
    unsigned long long r;
    asm("mov.b64 %0, {%1, %2};" : "=l"(r) : "f"(x), "f"(y));
    return r;
}
__device__ __forceinline__ float2 unpack2(unsigned long long v) {
    float2 r;
    asm("mov.b64 {%0, %1}, %2;" : "=f"(r.x), "=f"(r.y) : "l"(v));
    return r;
}

// ---------------- mark: batch mask per used vocab id (also zeroes g_nids) ----------
__global__ void k_mark(const int* __restrict__ docs,
                       const int* __restrict__ plen) {
    int b = blockIdx.x;
    __shared__ int tot;
    if (threadIdx.x == 0) {
        int s = 0;
        #pragma unroll
        for (int q = 0; q < P; q++) s += plen[b * P + q];
        tot = s;
        if (b == 0) g_nids = 0;   // no reader until k_compact (next kernel)
    }
    __syncthreads();
    unsigned bit = 1u << b;
    for (int tt = threadIdx.x; tt < tot; tt += blockDim.x)
        atomicOr(&g_mask[docs[b * DLEN + tt]], bit);
}

// ---------------- compact used ids + masks; block-aggregated atomics ---------------
__global__ void k_compact() {
    __shared__ int warp_off[8];
    __shared__ int block_base;
    int i = blockIdx.x * 256 + threadIdx.x;
    unsigned m = (i < V) ? g_mask[i] : 0u;
    bool has = (m != 0u);
    if (has) g_mask[i] = 0u;                     // self-clean for next call
    unsigned ballot = __ballot_sync(0xFFFFFFFFu, has);
    int w = threadIdx.x >> 5, lane = threadIdx.x & 31;
    if (lane == 0) warp_off[w] = __popc(ballot);
    __syncthreads();
    if (threadIdx.x == 0) {
        int tot = 0;
        #pragma unroll
        for (int j = 0; j < 8; j++) { int c = warp_off[j]; warp_off[j] = tot; tot += c; }
        block_base = tot ? atomicAdd(&g_nids, tot) : 0;
    }
    __syncthreads();
    if (has) {
        int slot = block_base + warp_off[w] + __popc(ballot & ((1u << lane) - 1u));
        g_ids[slot] = i;
        g_cmask[slot] = m;
        g_rank[i] = slot;
    }
}

// ---------------- q_rep = masked mean of query token embeddings ----------------
__global__ void k_qrep(const int* __restrict__ queries,
                       const int* __restrict__ qlen,
                       const float* __restrict__ emb) {
    int b = blockIdx.x;
    __shared__ int toks[LQ];
    if (threadIdx.x < LQ) toks[threadIdx.x] = queries[b * LQ + threadIdx.x];
    int len = qlen[b];
    __syncthreads();
    float inv = 1.0f / (float)len;
    int d = blockIdx.y * 256 + threadIdx.x;
    float s = 0.0f;
    for (int l = 0; l < len; l++) s += emb[(size_t)toks[l] * D + d];
    g_qrep[b * D + d] = s * inv;
}

// ---------------- skinny GEMM via FFMA2: C[32,2048] = A[32,2048] x W^(T) -------------
// grid (32, KSPLIT); one 64-wide k chunk per block; partials to g_part.
__global__ void k_gemm(const float* __restrict__ A,
                       const float* __restrict__ W,
                       int transW) {
    const int n0 = blockIdx.x * TILE_N;
    const int k0 = blockIdx.y * KB;
    __shared__ __align__(16) float As_t[KB][36];           // transposed A tile [k][row]
    __shared__ unsigned long long Ws2[KB][TILE_N + 1];     // dup pairs [k][n], pad

    const int t  = threadIdx.x;       // 256 threads
    const int tb = t >> 5;            // warp id 0..7 -> rows tb*4..tb*4+3
    const int tn = t & 31;

    #pragma unroll
    for (int i = 0; i < 8; i++) {
        int flat = t + i * 256;
        int bb = flat >> 6, kk = flat & 63;
        As_t[kk][bb] = A[bb * 2048 + k0 + kk];
    }
    if (!transW) {
        #pragma unroll
        for (int i = 0; i < 16; i++) {
            int flat = t + i * 256;
            int nn = flat >> 6, kk = flat & 63;
            float wv = W[(size_t)(n0 + nn) * 2048 + k0 + kk];
            Ws2[kk][nn] = pack2(wv, wv);
        }
    } else {
        #pragma unroll
        for (int i = 0; i < 16; i++) {
            int flat = t + i * 256;
            int nn = flat & 63, kk = flat >> 6;
            float wv = W[(size_t)(k0 + kk) * 2048 + n0 + nn];
            Ws2[kk][nn] = pack2(wv, wv);
        }
    }
    __syncthreads();

    unsigned long long acc00 = 0ull, acc01 = 0ull, acc10 = 0ull, acc11 = 0ull;
    #pragma unroll 16
    for (int k = 0; k < KB; k++) {
        ulonglong2 a = *(const ulonglong2*)&As_t[k][tb * 4];   // rows (4tb,4tb+1),(4tb+2,4tb+3)
        unsigned long long w0 = Ws2[k][tn];
        unsigned long long w1 = Ws2[k][tn + 32];
        acc00 = ffma2(a.x, w0, acc00);
        acc01 = ffma2(a.x, w1, acc01);
        acc10 = ffma2(a.y, w0, acc10);
        acc11 = ffma2(a.y, w1, acc11);
    }

    float* out = g_part + (size_t)blockIdx.y * 32 * 2048;
    float2 v00 = unpack2(acc00), v01 = unpack2(acc01);
    float2 v10 = unpack2(acc10), v11 = unpack2(acc11);
    out[(tb * 4 + 0) * 2048 + n0 + tn]      = v00.x;
    out[(tb * 4 + 1) * 2048 + n0 + tn]      = v00.y;
    out[(tb * 4 + 0) * 2048 + n0 + tn + 32] = v01.x;
    out[(tb * 4 + 1) * 2048 + n0 + tn + 32] = v01.y;
    out[(tb * 4 + 2) * 2048 + n0 + tn]      = v10.x;
    out[(tb * 4 + 3) * 2048 + n0 + tn]      = v10.y;
    out[(tb * 4 + 2) * 2048 + n0 + tn + 32] = v11.x;
    out[(tb * 4 + 3) * 2048 + n0 + tn + 32] = v11.y;
}

// vectorized partial reduce over 16384 float4; 128 blocks x 128 threads
__global__ void k_reduce(float* __restrict__ C,
                         const float* __restrict__ bias,
                         int addBias) {
    int idx = blockIdx.x * 128 + threadIdx.x;
    const float4* part4 = (const float4*)g_part;
    float4 s = make_float4(0.f, 0.f, 0.f, 0.f);
    #pragma unroll
    for (int sp = 0; sp < KSPLIT; sp++) {
        float4 x = part4[sp * 16384 + idx];
        s.x += x.x; s.y += x.y; s.z += x.z; s.w += x.w;
    }
    if (addBias) {
        float4 bb = ((const float4*)bias)[idx & 511];
        s.x += bb.x; s.y += bb.y; s.z += bb.z; s.w += bb.w;
    }
    ((float4*)C)[idx] = s;
}

// c[b] = q_enc[b] . bias
__global__ void k_qc(const float* __restrict__ bias) {
    int b = blockIdx.x;
    float s = 0.0f;
    for (int i = threadIdx.x; i < H; i += 256) s += g_qenc[b * H + i] * bias[i];
    __shared__ float red[256];
    red[threadIdx.x] = s;
    __syncthreads();
    for (int o = 128; o; o >>= 1) {
        if (threadIdx.x < o) red[threadIdx.x] += red[threadIdx.x + o];
        __syncthreads();
    }
    if (threadIdx.x == 0) g_c[b] = red[0];
}

// ---------------- ydot: per compact row, dot against ONLY the batches in its mask ----
// grid (VPAD/YROWS, KCH). 512 threads; block stages v k-chunk (32 KB) once;
// one warp per row, depth-2 row pipeline (4 outstanding LDG.128/lane).
__global__ __launch_bounds__(512) void k_ydot(const float* __restrict__ emb) {
    const int z  = blockIdx.y;
    const int m0 = blockIdx.x * YROWS;
    const int nids = g_nids;
    if (m0 >= nids) return;

    __shared__ float vs[32][256];    // v chunk [b][j]
    __shared__ int ids_s[YROWS];
    __shared__ unsigned mask_s[YROWS];

    const int t = threadIdx.x, w = t >> 5, lane = t & 31;

    #pragma unroll
    for (int i = 0; i < 4; i++) {
        int idx = t + i * 512;               // 0..2047 float4s
        int b = idx >> 6, j = idx & 63;
        *((float4*)&vs[b][j * 4]) = *(const float4*)(g_v + (size_t)b * D + z * 256 + j * 4);
    }
    if (t < YROWS) {
        int gi = m0 + t;
        bool val = gi < nids;
        ids_s[t]  = val ? g_ids[gi] : 0;
        mask_s[t] = val ? g_cmask[gi] : 0u;
    }
    __syncthreads();

    const int rbase = w * 16;                // warp w handles 16 rows
    const size_t zoff = (size_t)z * 256 + lane * 8;

    float4 pa0, pb0, pa1, pb1;
    {
        const float* rp = emb + (size_t)ids_s[rbase] * D + zoff;
        pa0 = ((const float4*)rp)[0]; pb0 = ((const float4*)rp)[1];
    }
    {
        const float* rp = emb + (size_t)ids_s[rbase + 1] * D + zoff;
        pa1 = ((const float4*)rp)[0]; pb1 = ((const float4*)rp)[1];
    }

    #pragma unroll 1
    for (int r = 0; r < 16; r += 2) {
        float4 ea = pa0, eb = pb0;
        if (r + 2 < 16) {
            const float* rp = emb + (size_t)ids_s[rbase + r + 2] * D + zoff;
            pa0 = ((const float4*)rp)[0]; pb0 = ((const float4*)rp)[1];
        }
        unsigned mask = mask_s[rbase + r];
        int slot = m0 + rbase + r;
        while (mask) {
            int b = __ffs(mask) - 1;
            mask &= mask - 1;
            const float* vp = &vs[b][lane * 8];
            float s = ea.x * vp[0] + ea.y * vp[1] + ea.z * vp[2] + ea.w * vp[3]
                    + eb.x * vp[4] + eb.y * vp[5] + eb.z * vp[6] + eb.w * vp[7];
            #pragma unroll
            for (int o = 16; o; o >>= 1) s += __shfl_xor_sync(0xFFFFFFFFu, s, o);
            if (lane == 0) g_yp[(size_t)slot * 256 + z * 32 + b] = s;
        }

        float4 ea1 = pa1, eb1 = pb1;
        if (r + 3 < 16) {
            const float* rp = emb + (size_t)ids_s[rbase + r + 3] * D + zoff;
            pa1 = ((const float4*)rp)[0]; pb1 = ((const float4*)rp)[1];
        }
        mask = mask_s[rbase + r + 1];
        slot = m0 + rbase + r + 1;
        while (mask) {
            int b = __ffs(mask) - 1;
            mask &= mask - 1;
            const float* vp = &vs[b][lane * 8];
            float s = ea1.x * vp[0] + ea1.y * vp[1] + ea1.z * vp[2] + ea1.w * vp[3]
                    + eb1.x * vp[4] + eb1.y * vp[5] + eb1.z * vp[6] + eb1.w * vp[7];
            #pragma unroll
            for (int o = 16; o; o >>= 1) s += __shfl_xor_sync(0xFFFFFFFFu, s, o);
            if (lane == 0) g_yp[(size_t)slot * 256 + z * 32 + b] = s;
        }
    }
}

// ---------------- scatter: score[b,p] = mean_token sum_z yp[rank[tok]][z][b] + c[b] --
__global__ void k_scatter(const int* __restrict__ docs,
                          const int* __restrict__ plen,
                          float* __restrict__ out) {
    const int bp = blockIdx.x;           // 512 blocks
    const int b = bp >> 4, p = bp & 15;
    const int t = threadIdx.x;           // 128 threads
    __shared__ int info[2];
    __shared__ float red[128];

    if (t == 0) {
        int start = 0;
        for (int q = 0; q < p; q++) start += plen[b * P + q];
        info[0] = start;
        info[1] = plen[b * P + p];
    }
    __syncthreads();
    const int start = info[0], len = info[1];

    float s = 0.0f;
    for (int tt = t; tt < len; tt += 128) {
        int tok = docs[b * DLEN + start + tt];
        const float* yb = g_yp + (size_t)g_rank[tok] * 256 + b;
        // fixed summation order over the 8 k-chunks -> deterministic
        float s01 = yb[0 * 32] + yb[1 * 32];
        float s23 = yb[2 * 32] + yb[3 * 32];
        float s45 = yb[4 * 32] + yb[5 * 32];
        float s67 = yb[6 * 32] + yb[7 * 32];
        s += (s01 + s23) + (s45 + s67);
    }
    red[t] = s;
    __syncthreads();
    for (int o = 64; o; o >>= 1) {
        if (t < o) red[t] += red[t + o];
        __syncthreads();
    }
    if (t == 0) {
        float denom = (float)(len > 0 ? len : 1);
        out[bp] = (len > 0) ? (red[0] / denom + g_c[b]) : 0.0f;
    }
}

// ---------------- launch ----------------
extern "C" void kernel_launch(void* const* d_in, const int* in_sizes, int n_in,
                              void* d_out, int out_size) {
    const int*   queries = (const int*)d_in[0];
    const int*   qlen    = (const int*)d_in[1];
    const int*   docs    = (const int*)d_in[2];
    const int*   plen    = (const int*)d_in[3];
    const float* emb     = (const float*)d_in[4];
    const float* W       = (const float*)d_in[5];
    const float* bias    = (const float*)d_in[6];
    float*       out     = (float*)d_out;

    float *qrep_p, *qenc_p, *v_p;
    cudaGetSymbolAddress((void**)&qrep_p, g_qrep);
    cudaGetSymbolAddress((void**)&qenc_p, g_qenc);
    cudaGetSymbolAddress((void**)&v_p, g_v);

    cudaStream_t s2;
    cudaStreamCreateWithFlags(&s2, cudaStreamNonBlocking);
    cudaEvent_t ef, ec, e3, ej;
    cudaEventCreateWithFlags(&ef, cudaEventDisableTiming);
    cudaEventCreateWithFlags(&ec, cudaEventDisableTiming);
    cudaEventCreateWithFlags(&e3, cudaEventDisableTiming);
    cudaEventCreateWithFlags(&ej, cudaEventDisableTiming);

    // fork: dedup pipeline (+qc later) on s2; encode chain on stream 0
    cudaEventRecord(ef, 0);
    cudaStreamWaitEvent(s2, ef, 0);
    k_mark<<<B, 256, 0, s2>>>(docs, plen);
    k_compact<<<(V + 255) / 256, 256, 0, s2>>>();
    cudaEventRecord(ec, s2);

    k_qrep<<<dim3(B, 8), 256>>>(queries, qlen, emb);
    k_gemm<<<dim3(2048 / TILE_N, KSPLIT), 256>>>(qrep_p, W, 0);
    k_reduce<<<128, 128>>>(qenc_p, bias, 1);
    cudaEventRecord(e3, 0);                        // qenc ready
    k_gemm<<<dim3(2048 / TILE_N, KSPLIT), 256>>>(qenc_p, W, 1);
    k_reduce<<<128, 128>>>(v_p, bias, 0);          // v ready

    // qc off the critical path, on s2 (needs qenc)
    cudaStreamWaitEvent(s2, e3, 0);
    k_qc<<<B, 256, 0, s2>>>(bias);
    cudaEventRecord(ej, s2);

    // ydot: needs ids+masks (ec) and v (stream 0 order)
    cudaStreamWaitEvent(0, ec, 0);
    k_ydot<<<dim3(VPAD / YROWS, KCH), 512>>>(emb);

    // scatter: needs ydot (stream 0) and qc (ej)
    cudaStreamWaitEvent(0, ej, 0);
    k_scatter<<<B * P, 128>>>(docs, plen, out);
}